// round 13
// baseline (speedup 1.0000x reference)
#include <cuda_runtime.h>
#include <cstdint>

// YOLO loss [4096,14,14,30] fp32 x2 -> scalar. 192.7 MB compulsory read.
// SPLIT-SOURCE fill (R12) with a DEEPER pipeline: 4 stages x 224-cell tiles.
// tgt (DRAM) via TMA bulk evict_first; pred (L2-resident via evict_last) via
// cp.async from all 448 threads. Persistent 1-CTA/SM, static schedule.

#define FEAT 30
#define BATCH 4096
#define NCELL (BATCH * 14 * 14)        // 802816
#define TILE 224                       // cells per tile; 802816 = 224*3584
#define NTILES (NCELL / TILE)          // 3584 exact
#define TPB 448                        // 14 warps
#define GRID 152                       // 1 CTA/SM
#define STAGES 4
#define TILE_BYTES (TILE * FEAT * 4)   // 26880 per tensor
#define STAGE_BYTES (2 * TILE_BYTES)   // 53760
#define SMEM_BUF_OFF 1024
#define SMEM_TOTAL (SMEM_BUF_OFF + STAGES * STAGE_BYTES)   // 216064

__device__ float g_partials[GRID];
__device__ unsigned int g_done = 0;

__device__ __forceinline__ uint32_t smem_u32(const void* p) {
    uint32_t a;
    asm("{ .reg .u64 t; cvta.to.shared.u64 t, %1; cvt.u32.u64 %0, t; }"
        : "=l"(p), "=r"(a) : );   // placeholder; replaced below
    return a;
}

// (correct version)
__device__ __forceinline__ uint32_t smem_addr_u32(const void* p) {
    uint32_t a;
    asm("{ .reg .u64 t; cvta.to.shared.u64 t, %1; cvt.u32.u64 %0, t; }"
        : "=r"(a) : "l"(p));
    return a;
}

__device__ __forceinline__ void mbar_init(uint32_t mbar, uint32_t count) {
    asm volatile("mbarrier.init.shared.b64 [%0], %1;" :: "r"(mbar), "r"(count) : "memory");
}

__device__ __forceinline__ void mbar_expect_tx(uint32_t mbar, uint32_t bytes) {
    asm volatile("mbarrier.arrive.expect_tx.shared.b64 _, [%0], %1;"
                 :: "r"(mbar), "r"(bytes) : "memory");
}

__device__ __forceinline__ void mbar_arrive(uint32_t mbar) {
    asm volatile("mbarrier.arrive.release.cta.shared::cta.b64 _, [%0];"
                 :: "r"(mbar) : "memory");
}

__device__ __forceinline__ void mbar_wait(uint32_t mbar, uint32_t phase) {
    asm volatile(
        "{\n\t"
        ".reg .pred P1;\n\t"
        "WAIT_LOOP_%=:\n\t"
        "mbarrier.try_wait.parity.acquire.cta.shared::cta.b64 P1, [%0], %1, 0x989680;\n\t"
        "@P1 bra.uni WAIT_DONE_%=;\n\t"
        "bra.uni WAIT_LOOP_%=;\n\t"
        "WAIT_DONE_%=:\n\t"
        "}"
        :: "r"(mbar), "r"(phase) : "memory");
}

__device__ __forceinline__ void bulk_g2s_pol(uint32_t dst, const void* src,
                                             uint32_t bytes, uint32_t mbar,
                                             uint64_t pol) {
    asm volatile(
        "cp.async.bulk.shared::cluster.global.mbarrier::complete_tx::bytes.L2::cache_hint "
        "[%0], [%1], %2, [%3], %4;"
        :: "r"(dst), "l"(src), "r"(bytes), "r"(mbar), "l"(pol) : "memory");
}

__device__ __forceinline__ void cp16_pol(uint32_t dst, const void* src, uint64_t pol) {
    asm volatile("cp.async.cg.shared.global.L2::cache_hint [%0], [%1], 16, %2;"
                 :: "r"(dst), "l"(src), "l"(pol) : "memory");
}

__device__ __forceinline__ uint64_t policy_evict_last() {
    uint64_t p;
    asm("createpolicy.fractional.L2::evict_last.b64 %0, 1.0;" : "=l"(p));
    return p;
}

__device__ __forceinline__ uint64_t policy_evict_first() {
    uint64_t p;
    asm("createpolicy.fractional.L2::evict_first.b64 %0, 1.0;" : "=l"(p));
    return p;
}

__device__ __forceinline__ float iou_box(float ax, float ay, float aw, float ah,
                                         float bx, float by, float bw, float bh) {
    float a_x1 = ax - aw * 0.5f, a_y1 = ay - ah * 0.5f;
    float a_x2 = ax + aw * 0.5f, a_y2 = ay + ah * 0.5f;
    float b_x1 = bx - bw * 0.5f, b_y1 = by - bh * 0.5f;
    float b_x2 = bx + bw * 0.5f, b_y2 = by + bh * 0.5f;
    float iw = fmaxf(fminf(a_x2, b_x2) - fmaxf(a_x1, b_x1), 0.0f);
    float ih = fmaxf(fminf(a_y2, b_y2) - fmaxf(a_y1, b_y1), 0.0f);
    float inter = iw * ih;
    float a1 = (a_x2 - a_x1) * (a_y2 - a_y1);
    float a2 = (b_x2 - b_x1) * (b_y2 - b_y1);
    return inter / (a1 + a2 - inter + 1e-6f);
}

__device__ __forceinline__ float cell_loss(const float* p, const float* t) {
    bool m = t[4] > 0.0f;
    float mf = m ? 1.0f : 0.0f;

    float ce0 = p[4] - t[4]; ce0 *= ce0;
    float ce1 = p[9] - t[9]; ce1 *= ce1;
    float noobj_conf = m ? 0.0f : (ce0 + ce1);

    float iou0 = iou_box(p[0], p[1], p[2], p[3], t[0], t[1], t[2], t[3]);
    float iou1 = iou_box(p[5], p[6], p[7], p[8], t[5], t[6], t[7], t[8]);
    bool best1 = iou1 > iou0;

    float pb0 = best1 ? p[5] : p[0];
    float pb1 = best1 ? p[6] : p[1];
    float pb2 = best1 ? p[7] : p[2];
    float pb3 = best1 ? p[8] : p[3];
    float pb4 = best1 ? p[9] : p[4];
    float tb0 = best1 ? t[5] : t[0];
    float tb1 = best1 ? t[6] : t[1];
    float tb2 = best1 ? t[7] : t[2];
    float tb3 = best1 ? t[8] : t[3];
    float tb4 = best1 ? t[9] : t[4];

    float dx = pb0 - tb0, dy = pb1 - tb1;
    float xy_loss = dx * dx + dy * dy;

    float pw = sqrtf(fabsf(pb2) + 1e-6f);
    float phh = sqrtf(fabsf(pb3) + 1e-6f);
    float tw = sqrtf(m ? tb2 : 1.0f);
    float th = sqrtf(m ? tb3 : 1.0f);
    float dw = pw - tw, dh = phh - th;
    float wh_loss = dw * dw + dh * dh;

    float dobj = pb4 - tb4;
    float nonbest = p[4] + p[9] - pb4;

    float cls = 0.0f;
#pragma unroll
    for (int c = 0; c < 20; c++) {
        float d = p[10 + c] - t[10 + c];
        cls += d * d;
    }

    return 5.0f * mf * (xy_loss + wh_loss)
         + mf * dobj * dobj
         + 0.5f * (noobj_conf + 0.5f * mf * nonbest * nonbest)
         + mf * cls;
}

__global__ void __launch_bounds__(TPB)
yolo_split4_kernel(const float* __restrict__ pred, const float* __restrict__ tgt,
                   float* __restrict__ out) {
    extern __shared__ char smem[];
    const uint32_t smem_base = smem_addr_u32(smem);
    const int tid = threadIdx.x;

    __shared__ float warp_sums[TPB / 32];
    __shared__ bool s_last;

    if (tid == 0) {
#pragma unroll
        for (int s = 0; s < STAGES; s++)
            mbar_init(smem_base + s * 8, 1);
        asm volatile("fence.proxy.async.shared::cta;" ::: "memory");
    }
    __syncthreads();

    const uint64_t pol_keep   = policy_evict_last();   // pred: stay in L2
    const uint64_t pol_stream = policy_evict_first();  // tgt: stream through

    // fill stage s with tile tt: pred half via per-thread cp.async (L2 source),
    // tgt half via TMA bulk (DRAM source). Always commits a cp.async group.
    auto issue = [&](int tt, int s) {
        uint32_t sbase = smem_base + SMEM_BUF_OFF + s * STAGE_BYTES;
        if (tt < NTILES) {
            const char* psrc = (const char*)pred + (size_t)tt * TILE_BYTES;
#pragma unroll
            for (int k = 0; k < 4; k++) {          // 26880/16/448 = 3.75 -> 4 w/ guard
                int off = (tid + k * TPB) * 16;
                if (off < TILE_BYTES)
                    cp16_pol(sbase + off, psrc + off, pol_keep);
            }
            if (tid == 0) {
                uint32_t mbar = smem_base + s * 8;
                mbar_expect_tx(mbar, TILE_BYTES);
                bulk_g2s_pol(sbase + TILE_BYTES,
                             (const char*)tgt + (size_t)tt * TILE_BYTES,
                             TILE_BYTES, mbar, pol_stream);
            }
        } else if (tid == 0) {
            mbar_arrive(smem_base + s * 8);
        }
        asm volatile("cp.async.commit_group;" ::: "memory");
    };

    // ---- prologue: fill all 4 stages ----
#pragma unroll
    for (int s = 0; s < STAGES; s++)
        issue((int)blockIdx.x + s * GRID, s);

    float acc = 0.0f;
    int it = 0;
    for (int tile = blockIdx.x; tile < NTILES; tile += GRID, it++) {
        const int st = it % STAGES;
        const uint32_t ph = (uint32_t)(it / STAGES) & 1u;

        asm volatile("cp.async.wait_group %0;" :: "n"(STAGES - 1) : "memory");
        mbar_wait(smem_base + st * 8, ph);
        __syncthreads();   // all threads' cp.async fills + TMA visible to all

        const char* buf = smem + SMEM_BUF_OFF + st * STAGE_BYTES;
        const float2* P2 = reinterpret_cast<const float2*>(buf + (tid >> 1) * (FEAT * 4));
        (void)P2;
        // each thread owns cell (tid % TILE); 448 threads, 224 cells -> 2 threads/cell?
        // No: one cell per thread for tid < TILE, second half handles none.
        // Better: each thread handles cell tid/2? Keep it simple & correct:
        // threads 0..223 do cells, threads 224..447 do cells too (split halves).
        float lsum = 0.0f;
        {
            int cell = tid % TILE;
            int half = tid / TILE;           // 0 or 1: each cell computed by ONE thread only if half==0
            if (half == 0) {
                const float2* Pp = reinterpret_cast<const float2*>(buf + cell * (FEAT * 4));
                const float2* Tt = reinterpret_cast<const float2*>(buf + TILE_BYTES + cell * (FEAT * 4));
                float p[FEAT], t[FEAT];
#pragma unroll
                for (int i = 0; i < FEAT / 2; i++) {
                    float2 v = Pp[i]; p[2 * i] = v.x; p[2 * i + 1] = v.y;
                }
#pragma unroll
                for (int i = 0; i < FEAT / 2; i++) {
                    float2 v = Tt[i]; t[2 * i] = v.x; t[2 * i + 1] = v.y;
                }
                lsum = cell_loss(p, t);
            }
        }

        __syncthreads();                 // stage fully read
        issue(tile + STAGES * GRID, st); // refill; flops overlap

        acc += lsum;
    }

    // ---- block reduction ----
#pragma unroll
    for (int off = 16; off > 0; off >>= 1)
        acc += __shfl_down_sync(0xFFFFFFFFu, acc, off);
    int lane = tid & 31;
    int wid  = tid >> 5;
    if (lane == 0) warp_sums[wid] = acc;
    __syncthreads();
    if (tid == 0) {
        float v = 0.0f;
#pragma unroll
        for (int w = 0; w < TPB / 32; w++) v += warp_sums[w];
        g_partials[blockIdx.x] = v;
        __threadfence();
        unsigned int done = atomicAdd(&g_done, 1u);
        s_last = (done == (unsigned)(gridDim.x - 1));
    }
    __syncthreads();

    if (s_last) {
        __threadfence();
        float v = 0.0f;
        for (int i = tid; i < GRID; i += TPB)
            v += g_partials[i];
#pragma unroll
        for (int off = 16; off > 0; off >>= 1)
            v += __shfl_down_sync(0xFFFFFFFFu, v, off);
        if (lane == 0) warp_sums[wid] = v;
        __syncthreads();
        if (tid == 0) {
            float tot = 0.0f;
#pragma unroll
            for (int w = 0; w < TPB / 32; w++) tot += warp_sums[w];
            out[0] = tot / (float)BATCH;
            g_done = 0;
        }
    }
}

extern "C" void kernel_launch(void* const* d_in, const int* in_sizes, int n_in,
                              void* d_out, int out_size) {
    const float* pred = (const float*)d_in[0];
    const float* tgt  = (const float*)d_in[1];
    float* out = (float*)d_out;
    cudaFuncSetAttribute(yolo_split4_kernel,
                         cudaFuncAttributeMaxDynamicSharedMemorySize, SMEM_TOTAL);
    yolo_split4_kernel<<<GRID, TPB, SMEM_TOTAL>>>(pred, tgt, out);
}